// round 1
// baseline (speedup 1.0000x reference)
#include <cuda_runtime.h>
#include <cuda_bf16.h>
#include <math.h>

// Problem constants
#define B_ 2
#define T_ 2048
#define C_ 2048
#define H_ 16
#define KVH_ 4
#define D_ 128
#define M_ (B_ * T_)          // 4096
#define KVC_ (KVH_ * D_)      // 512
#define SCALE_ 0.08838834764831845f
#define RMS_EPS 1.1920929e-07f

// ---------------------------------------------------------------------------
// Scratch (device globals; no allocation allowed)
// ---------------------------------------------------------------------------
__device__ float g_q[(size_t)M_ * C_];    // 32 MiB
__device__ float g_k[(size_t)M_ * KVC_];  // 8 MiB
__device__ float g_v[(size_t)M_ * KVC_];  // 8 MiB
__device__ float g_y[(size_t)M_ * C_];    // 32 MiB

// ---------------------------------------------------------------------------
// Generic fp32 SGEMM: C = A(MxK) @ B(KxN). M,N multiples of 128; K of 16.
// 128x128 block tile, BK=16, 256 threads, 8x8 per thread.
// ---------------------------------------------------------------------------
#define GBM 128
#define GBN 128
#define GBK 16
#define GTM 8
#define GTN 8

__global__ __launch_bounds__(256) void sgemm_kernel(
    const float* __restrict__ A, const float* __restrict__ Bm,
    float* __restrict__ Cm, int M, int N, int K)
{
    __shared__ float As[GBK][GBM];       // transposed A tile
    __shared__ float Bs[GBK][GBN];

    const int bx = blockIdx.x;           // N tile
    const int by = blockIdx.y;           // M tile
    const int tid = threadIdx.x;
    const int tx = tid & 15;
    const int ty = tid >> 4;

    const float* Ab = A + (size_t)by * GBM * K;
    const float* Bb = Bm + (size_t)bx * GBN;

    float acc[GTM][GTN];
    #pragma unroll
    for (int i = 0; i < GTM; i++)
        #pragma unroll
        for (int j = 0; j < GTN; j++) acc[i][j] = 0.f;

    for (int k0 = 0; k0 < K; k0 += GBK) {
        // Load A tile: 128 rows x 16 cols = 512 float4 (2 per thread)
        #pragma unroll
        for (int i = 0; i < 2; i++) {
            int idx = tid + i * 256;
            int r = idx >> 2;
            int c4 = (idx & 3) << 2;
            float4 va = *(const float4*)(Ab + (size_t)r * K + k0 + c4);
            As[c4 + 0][r] = va.x;
            As[c4 + 1][r] = va.y;
            As[c4 + 2][r] = va.z;
            As[c4 + 3][r] = va.w;
        }
        // Load B tile: 16 rows x 128 cols = 512 float4 (2 per thread)
        #pragma unroll
        for (int i = 0; i < 2; i++) {
            int idx = tid + i * 256;
            int r = idx >> 5;
            int c4 = (idx & 31) << 2;
            *(float4*)(&Bs[r][c4]) = *(const float4*)(Bb + (size_t)(k0 + r) * N + c4);
        }
        __syncthreads();

        #pragma unroll
        for (int k = 0; k < GBK; k++) {
            float af[GTM], bf[GTN];
            #pragma unroll
            for (int i = 0; i < GTM; i++) af[i] = As[k][ty * GTM + i];
            #pragma unroll
            for (int j = 0; j < GTN; j++) bf[j] = Bs[k][tx * GTN + j];
            #pragma unroll
            for (int i = 0; i < GTM; i++)
                #pragma unroll
                for (int j = 0; j < GTN; j++)
                    acc[i][j] = fmaf(af[i], bf[j], acc[i][j]);
        }
        __syncthreads();
    }

    float* Cb = Cm + (size_t)(by * GBM + ty * GTM) * N + bx * GBN + tx * GTN;
    #pragma unroll
    for (int i = 0; i < GTM; i++) {
        #pragma unroll
        for (int j = 0; j < GTN; j += 4) {
            float4 vv = make_float4(acc[i][j], acc[i][j + 1], acc[i][j + 2], acc[i][j + 3]);
            *(float4*)(Cb + (size_t)i * N + j) = vv;
        }
    }
}

// ---------------------------------------------------------------------------
// Fused RoPE (half-dim) + RMSNorm over head_dim=128.
// One block (128 threads) per (b, t, head) row.
// ---------------------------------------------------------------------------
__global__ __launch_bounds__(128) void rope_rms_kernel(
    float* __restrict__ x, const float* __restrict__ cs,
    const float* __restrict__ sn, int nh)
{
    __shared__ float buf[128];
    __shared__ float red[4];
    const int row = blockIdx.x;
    const int t = (row / nh) % T_;
    const int tid = threadIdx.x;

    buf[tid] = x[(size_t)row * D_ + tid];
    __syncthreads();

    float r;
    if (tid < 64) {
        float c = cs[t * 64 + tid];
        float s = sn[t * 64 + tid];
        r = buf[tid] * c + buf[tid + 64] * s;
    } else {
        int j = tid - 64;
        float c = cs[t * 64 + j];
        float s = sn[t * 64 + j];
        r = -buf[j] * s + buf[j + 64] * c;
    }

    float sq = r * r;
    #pragma unroll
    for (int o = 16; o > 0; o >>= 1) sq += __shfl_xor_sync(0xffffffffu, sq, o);
    if ((tid & 31) == 0) red[tid >> 5] = sq;
    __syncthreads();
    float tot = red[0] + red[1] + red[2] + red[3];
    x[(size_t)row * D_ + tid] = r * rsqrtf(tot * (1.f / 128.f) + RMS_EPS);
}

// ---------------------------------------------------------------------------
// Flash attention (causal, GQA rep=4), fp32.
// Br=Bc=64, d=128, 256 threads. Dynamic smem:
//   Qs[64][132] + KVs[64][132] + Ss[64][65] + m[64] + l[64] + alpha[64]
// ---------------------------------------------------------------------------
#define FA_BR 64
#define FA_BC 64
#define FA_DP 132   // padded row stride for Q/KV tiles (mult of 4, bank-staggered)
#define FA_SP 65    // padded row stride for S tile

__global__ __launch_bounds__(256) void flash_attn_kernel(
    const float* __restrict__ q, const float* __restrict__ k,
    const float* __restrict__ v, float* __restrict__ y)
{
    extern __shared__ float sm[];
    float* Qs  = sm;                        // 64*132
    float* KVs = Qs + FA_BR * FA_DP;        // 64*132
    float* Ss  = KVs + FA_BC * FA_DP;       // 64*65
    float* m_s = Ss + FA_BR * FA_SP;        // 64
    float* l_s = m_s + FA_BR;               // 64
    float* a_s = l_s + FA_BR;               // 64

    const int tid = threadIdx.x;
    const int tx = tid & 15;
    const int ty = tid >> 4;
    const int bh = blockIdx.y;
    const int b = bh >> 4;
    const int h = bh & 15;
    const int kvh = h >> 2;
    const int q0 = blockIdx.x * FA_BR;

    const float* qbase = q + (size_t)b * T_ * C_ + h * D_;       // row stride C_
    const float* kbase = k + (size_t)b * T_ * KVC_ + kvh * D_;   // row stride KVC_
    const float* vbase = v + (size_t)b * T_ * KVC_ + kvh * D_;

    // Load Q tile (64 x 128 = 2048 float4, 8 per thread)
    #pragma unroll
    for (int i = 0; i < 8; i++) {
        int idx = tid + i * 256;
        int r = idx >> 5;
        int c = (idx & 31) << 2;
        float4 vv = *(const float4*)(qbase + (size_t)(q0 + r) * C_ + c);
        float* d = &Qs[r * FA_DP + c];
        d[0] = vv.x; d[1] = vv.y; d[2] = vv.z; d[3] = vv.w;
    }
    if (tid < FA_BR) { m_s[tid] = -INFINITY; l_s[tid] = 0.f; }

    float acc[4][8];
    #pragma unroll
    for (int i = 0; i < 4; i++)
        #pragma unroll
        for (int j = 0; j < 8; j++) acc[i][j] = 0.f;
    __syncthreads();

    const int srow0 = ty * 4;   // S-phase rows (also PV rows)
    const int scol0 = tx * 4;   // S-phase cols
    const int pcol0 = tx * 8;   // PV-phase cols

    for (int kt = 0; kt <= blockIdx.x; kt++) {
        const int k0 = kt * FA_BC;
        // Load K tile
        #pragma unroll
        for (int i = 0; i < 8; i++) {
            int idx = tid + i * 256;
            int r = idx >> 5;
            int c = (idx & 31) << 2;
            float4 vv = *(const float4*)(kbase + (size_t)(k0 + r) * KVC_ + c);
            float* d = &KVs[r * FA_DP + c];
            d[0] = vv.x; d[1] = vv.y; d[2] = vv.z; d[3] = vv.w;
        }
        __syncthreads();

        // S = Q @ K^T
        float sacc[4][4];
        #pragma unroll
        for (int i = 0; i < 4; i++)
            #pragma unroll
            for (int j = 0; j < 4; j++) sacc[i][j] = 0.f;
        for (int dd = 0; dd < D_; dd++) {
            float af[4], bf[4];
            #pragma unroll
            for (int i = 0; i < 4; i++) af[i] = Qs[(srow0 + i) * FA_DP + dd];
            #pragma unroll
            for (int j = 0; j < 4; j++) bf[j] = KVs[(scol0 + j) * FA_DP + dd];
            #pragma unroll
            for (int i = 0; i < 4; i++)
                #pragma unroll
                for (int j = 0; j < 4; j++)
                    sacc[i][j] = fmaf(af[i], bf[j], sacc[i][j]);
        }
        const bool diag = (kt == blockIdx.x);
        #pragma unroll
        for (int i = 0; i < 4; i++) {
            #pragma unroll
            for (int j = 0; j < 4; j++) {
                float sv = sacc[i][j] * SCALE_;
                if (diag && (k0 + scol0 + j > q0 + srow0 + i)) sv = -INFINITY;
                Ss[(srow0 + i) * FA_SP + scol0 + j] = sv;
            }
        }
        __syncthreads();

        // Online softmax per row (threads 0..63)
        if (tid < FA_BR) {
            const int r = tid;
            float mo = m_s[r];
            float mx = mo;
            #pragma unroll 8
            for (int c = 0; c < FA_BC; c++) mx = fmaxf(mx, Ss[r * FA_SP + c]);
            float alpha = __expf(mo - mx);
            float sum = 0.f;
            #pragma unroll 8
            for (int c = 0; c < FA_BC; c++) {
                float p = __expf(Ss[r * FA_SP + c] - mx);
                Ss[r * FA_SP + c] = p;
                sum += p;
            }
            l_s[r] = l_s[r] * alpha + sum;
            m_s[r] = mx;
            a_s[r] = alpha;
        }
        __syncthreads();

        // Rescale accumulator
        #pragma unroll
        for (int i = 0; i < 4; i++) {
            float al = a_s[srow0 + i];
            #pragma unroll
            for (int j = 0; j < 8; j++) acc[i][j] *= al;
        }

        // Load V tile (overwrite KVs)
        #pragma unroll
        for (int i = 0; i < 8; i++) {
            int idx = tid + i * 256;
            int r = idx >> 5;
            int c = (idx & 31) << 2;
            float4 vv = *(const float4*)(vbase + (size_t)(k0 + r) * KVC_ + c);
            float* d = &KVs[r * FA_DP + c];
            d[0] = vv.x; d[1] = vv.y; d[2] = vv.z; d[3] = vv.w;
        }
        __syncthreads();

        // acc += P @ V
        for (int kk = 0; kk < FA_BC; kk++) {
            float af[4];
            #pragma unroll
            for (int i = 0; i < 4; i++) af[i] = Ss[(srow0 + i) * FA_SP + kk];
            float4 b0 = *(const float4*)(&KVs[kk * FA_DP + pcol0]);
            float4 b1 = *(const float4*)(&KVs[kk * FA_DP + pcol0 + 4]);
            float bf[8] = {b0.x, b0.y, b0.z, b0.w, b1.x, b1.y, b1.z, b1.w};
            #pragma unroll
            for (int i = 0; i < 4; i++)
                #pragma unroll
                for (int j = 0; j < 8; j++)
                    acc[i][j] = fmaf(af[i], bf[j], acc[i][j]);
        }
        __syncthreads();
    }

    // Epilogue: divide by l, write y (B,T,H,D)
    float* ybase = y + (size_t)b * T_ * C_ + h * D_;
    #pragma unroll
    for (int i = 0; i < 4; i++) {
        int r = srow0 + i;
        float inv = 1.f / l_s[r];
        float4 o0 = make_float4(acc[i][0] * inv, acc[i][1] * inv, acc[i][2] * inv, acc[i][3] * inv);
        float4 o1 = make_float4(acc[i][4] * inv, acc[i][5] * inv, acc[i][6] * inv, acc[i][7] * inv);
        float* d = ybase + (size_t)(q0 + r) * C_ + pcol0;
        *(float4*)(d) = o0;
        *(float4*)(d + 4) = o1;
    }
}

// ---------------------------------------------------------------------------
// Launch
// ---------------------------------------------------------------------------
extern "C" void kernel_launch(void* const* d_in, const int* in_sizes, int n_in,
                              void* d_out, int out_size)
{
    const float* x   = (const float*)d_in[0];
    const float* cs  = (const float*)d_in[1];
    const float* sn  = (const float*)d_in[2];
    const float* Wq  = (const float*)d_in[3];
    const float* Wk  = (const float*)d_in[4];
    const float* Wv  = (const float*)d_in[5];
    const float* Wo  = (const float*)d_in[6];
    float* out = (float*)d_out;

    float *qp, *kp, *vp, *yp;
    cudaGetSymbolAddress((void**)&qp, g_q);
    cudaGetSymbolAddress((void**)&kp, g_k);
    cudaGetSymbolAddress((void**)&vp, g_v);
    cudaGetSymbolAddress((void**)&yp, g_y);

    const int fa_smem = (FA_BR * FA_DP + FA_BC * FA_DP + FA_BR * FA_SP + 3 * FA_BR) * 4;
    cudaFuncSetAttribute(flash_attn_kernel, cudaFuncAttributeMaxDynamicSharedMemorySize, fa_smem);

    dim3 blk256(256);
    // Projections
    sgemm_kernel<<<dim3(C_ / GBN, M_ / GBM), blk256>>>(x, Wq, qp, M_, C_, C_);
    sgemm_kernel<<<dim3(KVC_ / GBN, M_ / GBM), blk256>>>(x, Wk, kp, M_, KVC_, C_);
    sgemm_kernel<<<dim3(KVC_ / GBN, M_ / GBM), blk256>>>(x, Wv, vp, M_, KVC_, C_);
    // RoPE + RMSNorm
    rope_rms_kernel<<<M_ * H_, 128>>>(qp, cs, sn, H_);
    rope_rms_kernel<<<M_ * KVH_, 128>>>(kp, cs, sn, KVH_);
    // Attention
    flash_attn_kernel<<<dim3(T_ / FA_BR, B_ * H_), blk256, fa_smem>>>(qp, kp, vp, yp);
    // Output projection
    sgemm_kernel<<<dim3(C_ / GBN, M_ / GBM), blk256>>>(yp, Wo, out, M_, C_, C_);
}

// round 2
// speedup vs baseline: 3.0737x; 3.0737x over previous
#include <cuda_runtime.h>
#include <cuda_bf16.h>
#include <math.h>

// Problem constants
#define B_ 2
#define T_ 2048
#define C_ 2048
#define H_ 16
#define KVH_ 4
#define D_ 128
#define M_ (B_ * T_)          // 4096
#define KVC_ (KVH_ * D_)      // 512
#define SCALE_ 0.08838834764831845f
#define RMS_EPS 1.1920929e-07f

// ---------------------------------------------------------------------------
// Scratch (device globals; no allocation allowed)
// ---------------------------------------------------------------------------
__device__ float g_q[(size_t)M_ * C_];    // 32 MiB
__device__ float g_k[(size_t)M_ * KVC_];  // 8 MiB
__device__ float g_v[(size_t)M_ * KVC_];  // 8 MiB
__device__ float g_y[(size_t)M_ * C_];    // 32 MiB

// ---------------------------------------------------------------------------
// tf32 helpers
// ---------------------------------------------------------------------------
__device__ __forceinline__ float tf32r(float x) {
    unsigned u;
    asm("cvt.rna.tf32.f32 %0, %1;" : "=r"(u) : "f"(x));
    return __uint_as_float(u);
}

// D(16x8) += A(16x8) * B(8x8), tf32 inputs, fp32 accum
__device__ __forceinline__ void mma_tf32(float* c, const float* a, const float* b) {
    const unsigned* A = reinterpret_cast<const unsigned*>(a);
    const unsigned* Bv = reinterpret_cast<const unsigned*>(b);
    asm volatile(
        "mma.sync.aligned.m16n8k8.row.col.f32.tf32.tf32.f32 "
        "{%0,%1,%2,%3}, {%4,%5,%6,%7}, {%8,%9}, {%0,%1,%2,%3};\n"
        : "+f"(c[0]), "+f"(c[1]), "+f"(c[2]), "+f"(c[3])
        : "r"(A[0]), "r"(A[1]), "r"(A[2]), "r"(A[3]), "r"(Bv[0]), "r"(Bv[1]));
}

// ---------------------------------------------------------------------------
// tf32 GEMM: C = A(MxK) @ B(KxN). M,N mult of 128, K mult of 32.
// 128x128x32 block tile, 256 threads (8 warps, 2x4), warp tile 64x32.
// ---------------------------------------------------------------------------
#define GBM 128
#define GBN 128
#define GBK 32
#define A_ST 36    // As row stride (floats): bank = 4r+c (conflict free)
#define B_ST 136   // Bs row stride (floats): bank = 8r+c (conflict free)

__global__ __launch_bounds__(256, 1) void gemm_tf32(
    const float* __restrict__ A, const float* __restrict__ Bm,
    float* __restrict__ Cm, int M, int N, int K)
{
    __shared__ float As[GBM * A_ST];
    __shared__ float Bs[GBK * B_ST];

    const int tid = threadIdx.x;
    const int lane = tid & 31;
    const int wid = tid >> 5;
    const int t4 = lane >> 2;
    const int tm4 = lane & 3;
    const int wy = wid & 1;      // 2 warps along M
    const int wx = wid >> 1;     // 4 warps along N

    const float* Ab = A + (size_t)blockIdx.y * GBM * K;
    const float* Bb = Bm + (size_t)blockIdx.x * GBN;

    float acc[4][4][4];
    #pragma unroll
    for (int i = 0; i < 4; i++)
        #pragma unroll
        for (int j = 0; j < 4; j++)
            #pragma unroll
            for (int r = 0; r < 4; r++) acc[i][j][r] = 0.f;

    for (int k0 = 0; k0 < K; k0 += GBK) {
        // A tile: 128x32 = 1024 float4, 4 per thread
        #pragma unroll
        for (int i = 0; i < 4; i++) {
            int idx = tid + i * 256;
            int r = idx >> 3;
            int c = (idx & 7) << 2;
            float4 v = *(const float4*)(Ab + (size_t)r * K + k0 + c);
            float* d = &As[r * A_ST + c];
            d[0] = tf32r(v.x); d[1] = tf32r(v.y); d[2] = tf32r(v.z); d[3] = tf32r(v.w);
        }
        // B tile: 32x128 = 1024 float4, 4 per thread
        #pragma unroll
        for (int i = 0; i < 4; i++) {
            int idx = tid + i * 256;
            int r = idx >> 5;
            int c = (idx & 31) << 2;
            float4 v = *(const float4*)(Bb + (size_t)(k0 + r) * N + c);
            float* d = &Bs[r * B_ST + c];
            d[0] = tf32r(v.x); d[1] = tf32r(v.y); d[2] = tf32r(v.z); d[3] = tf32r(v.w);
        }
        __syncthreads();

        #pragma unroll
        for (int ks = 0; ks < GBK; ks += 8) {
            float afr[4][4], bfr[4][2];
            #pragma unroll
            for (int mi = 0; mi < 4; mi++) {
                int rb = wy * 64 + mi * 16;
                afr[mi][0] = As[(rb + t4) * A_ST + ks + tm4];
                afr[mi][1] = As[(rb + 8 + t4) * A_ST + ks + tm4];
                afr[mi][2] = As[(rb + t4) * A_ST + ks + tm4 + 4];
                afr[mi][3] = As[(rb + 8 + t4) * A_ST + ks + tm4 + 4];
            }
            #pragma unroll
            for (int ni = 0; ni < 4; ni++) {
                int cb = wx * 32 + ni * 8;
                bfr[ni][0] = Bs[(ks + tm4) * B_ST + cb + t4];
                bfr[ni][1] = Bs[(ks + tm4 + 4) * B_ST + cb + t4];
            }
            #pragma unroll
            for (int mi = 0; mi < 4; mi++)
                #pragma unroll
                for (int ni = 0; ni < 4; ni++)
                    mma_tf32(acc[mi][ni], afr[mi], bfr[ni]);
        }
        __syncthreads();
    }

    // Epilogue: c0,c1 -> (row, col..col+1); c2,c3 -> (row+8, ...)
    #pragma unroll
    for (int mi = 0; mi < 4; mi++) {
        int row = blockIdx.y * GBM + wy * 64 + mi * 16 + t4;
        #pragma unroll
        for (int ni = 0; ni < 4; ni++) {
            int col = blockIdx.x * GBN + wx * 32 + ni * 8 + tm4 * 2;
            *(float2*)(Cm + (size_t)row * N + col) = make_float2(acc[mi][ni][0], acc[mi][ni][1]);
            *(float2*)(Cm + (size_t)(row + 8) * N + col) = make_float2(acc[mi][ni][2], acc[mi][ni][3]);
        }
    }
}

// ---------------------------------------------------------------------------
// Fused RoPE (half-dim) + RMSNorm over head_dim=128.
// ---------------------------------------------------------------------------
__global__ __launch_bounds__(128) void rope_rms_kernel(
    float* __restrict__ x, const float* __restrict__ cs,
    const float* __restrict__ sn, int nh)
{
    __shared__ float buf[128];
    __shared__ float red[4];
    const int row = blockIdx.x;
    const int t = (row / nh) % T_;
    const int tid = threadIdx.x;

    buf[tid] = x[(size_t)row * D_ + tid];
    __syncthreads();

    float r;
    if (tid < 64) {
        float c = cs[t * 64 + tid];
        float s = sn[t * 64 + tid];
        r = buf[tid] * c + buf[tid + 64] * s;
    } else {
        int j = tid - 64;
        float c = cs[t * 64 + j];
        float s = sn[t * 64 + j];
        r = -buf[j] * s + buf[j + 64] * c;
    }

    float sq = r * r;
    #pragma unroll
    for (int o = 16; o > 0; o >>= 1) sq += __shfl_xor_sync(0xffffffffu, sq, o);
    if ((tid & 31) == 0) red[tid >> 5] = sq;
    __syncthreads();
    float tot = red[0] + red[1] + red[2] + red[3];
    x[(size_t)row * D_ + tid] = r * rsqrtf(tot * (1.f / 128.f) + RMS_EPS);
}

// ---------------------------------------------------------------------------
// Flash attention (causal, GQA rep=4), tf32 mma, fp32 accum.
// Br=Bc=64, d=128, 256 threads (8 warps).
// Warp layout: wy = wid&1 (2 x 32 rows), wx = wid>>1.
//   S phase: warp tile 32x16 (wx covers 4 x 16 cols)
//   PV phase: warp tile 32x32 (wx covers 4 x 32 cols of d=128)
// ---------------------------------------------------------------------------
#define FA_BR 64
#define FA_BC 64
#define Q_ST 132
#define K_ST 132
#define V_ST 136
#define S_ST 68

#define FA_SMEM_FLOATS (FA_BR * Q_ST + FA_BC * K_ST + FA_BC * V_ST + FA_BR * S_ST + 3 * FA_BR)

__global__ __launch_bounds__(256, 1) void flash_attn_tf32(
    const float* __restrict__ q, const float* __restrict__ k,
    const float* __restrict__ v, float* __restrict__ y)
{
    extern __shared__ float sm[];
    float* Qs = sm;                          // 64 x 132
    float* Ks = Qs + FA_BR * Q_ST;           // 64 x 132
    float* Vs = Ks + FA_BC * K_ST;           // 64 x 136
    float* Ss = Vs + FA_BC * V_ST;           // 64 x 68
    float* m_s = Ss + FA_BR * S_ST;
    float* l_s = m_s + FA_BR;
    float* a_s = l_s + FA_BR;

    const int tid = threadIdx.x;
    const int lane = tid & 31;
    const int wid = tid >> 5;
    const int t4 = lane >> 2;
    const int tm4 = lane & 3;
    const int wy = wid & 1;
    const int wx = wid >> 1;

    const int bh = blockIdx.y;
    const int b = bh >> 4;
    const int h = bh & 15;
    const int kvh = h >> 2;
    const int q0 = blockIdx.x * FA_BR;

    const float* qbase = q + (size_t)b * T_ * C_ + h * D_;
    const float* kbase = k + (size_t)b * T_ * KVC_ + kvh * D_;
    const float* vbase = v + (size_t)b * T_ * KVC_ + kvh * D_;

    // Load Q tile (64x128), convert to tf32
    #pragma unroll
    for (int i = 0; i < 8; i++) {
        int idx = tid + i * 256;
        int r = idx >> 5;
        int c = (idx & 31) << 2;
        float4 vv = *(const float4*)(qbase + (size_t)(q0 + r) * C_ + c);
        float* d = &Qs[r * Q_ST + c];
        d[0] = tf32r(vv.x); d[1] = tf32r(vv.y); d[2] = tf32r(vv.z); d[3] = tf32r(vv.w);
    }
    if (tid < FA_BR) { m_s[tid] = -INFINITY; l_s[tid] = 0.f; }

    float o[2][4][4];
    #pragma unroll
    for (int i = 0; i < 2; i++)
        #pragma unroll
        for (int j = 0; j < 4; j++)
            #pragma unroll
            for (int r = 0; r < 4; r++) o[i][j][r] = 0.f;
    __syncthreads();

    for (int kt = 0; kt <= blockIdx.x; kt++) {
        const int k0 = kt * FA_BC;
        // Load K and V tiles (each 64x128)
        #pragma unroll
        for (int i = 0; i < 8; i++) {
            int idx = tid + i * 256;
            int r = idx >> 5;
            int c = (idx & 31) << 2;
            float4 kv = *(const float4*)(kbase + (size_t)(k0 + r) * KVC_ + c);
            float* dk = &Ks[r * K_ST + c];
            dk[0] = tf32r(kv.x); dk[1] = tf32r(kv.y); dk[2] = tf32r(kv.z); dk[3] = tf32r(kv.w);
            float4 vv = *(const float4*)(vbase + (size_t)(k0 + r) * KVC_ + c);
            float* dv = &Vs[r * V_ST + c];
            dv[0] = tf32r(vv.x); dv[1] = tf32r(vv.y); dv[2] = tf32r(vv.z); dv[3] = tf32r(vv.w);
        }
        __syncthreads();

        // S = Q @ K^T  (warp tile 32x16)
        float sacc[2][2][4];
        #pragma unroll
        for (int i = 0; i < 2; i++)
            #pragma unroll
            for (int j = 0; j < 2; j++)
                #pragma unroll
                for (int r = 0; r < 4; r++) sacc[i][j][r] = 0.f;

        #pragma unroll
        for (int ks = 0; ks < D_; ks += 8) {
            float afr[2][4], bfr[2][2];
            #pragma unroll
            for (int mi = 0; mi < 2; mi++) {
                int rb = wy * 32 + mi * 16;
                afr[mi][0] = Qs[(rb + t4) * Q_ST + ks + tm4];
                afr[mi][1] = Qs[(rb + 8 + t4) * Q_ST + ks + tm4];
                afr[mi][2] = Qs[(rb + t4) * Q_ST + ks + tm4 + 4];
                afr[mi][3] = Qs[(rb + 8 + t4) * Q_ST + ks + tm4 + 4];
            }
            #pragma unroll
            for (int ni = 0; ni < 2; ni++) {
                int cb = wx * 16 + ni * 8;
                // B[k][j] = K[j][k]
                bfr[ni][0] = Ks[(cb + t4) * K_ST + ks + tm4];
                bfr[ni][1] = Ks[(cb + t4) * K_ST + ks + tm4 + 4];
            }
            #pragma unroll
            for (int mi = 0; mi < 2; mi++)
                #pragma unroll
                for (int ni = 0; ni < 2; ni++)
                    mma_tf32(sacc[mi][ni], afr[mi], bfr[ni]);
        }

        // Scale + causal mask + store S
        const bool diag = (kt == blockIdx.x);
        #pragma unroll
        for (int mi = 0; mi < 2; mi++) {
            #pragma unroll
            for (int ni = 0; ni < 2; ni++) {
                int rA = wy * 32 + mi * 16 + t4;
                int cA = wx * 16 + ni * 8 + tm4 * 2;
                #pragma unroll
                for (int half = 0; half < 2; half++) {
                    int r = rA + half * 8;
                    float v0 = sacc[mi][ni][half * 2 + 0] * SCALE_;
                    float v1 = sacc[mi][ni][half * 2 + 1] * SCALE_;
                    if (diag) {
                        if (cA > r) v0 = -INFINITY;
                        if (cA + 1 > r) v1 = -INFINITY;
                    }
                    *(float2*)(&Ss[r * S_ST + cA]) = make_float2(v0, v1);
                }
            }
        }
        __syncthreads();

        // Online softmax: 4 threads per row, 16 cols each
        {
            const int srow = tid >> 2;
            const int ssub = tid & 3;
            float* Srow = Ss + srow * S_ST + ssub * 16;
            float mo = m_s[srow];
            float mx = mo;
            #pragma unroll
            for (int j = 0; j < 16; j++) mx = fmaxf(mx, Srow[j]);
            mx = fmaxf(mx, __shfl_xor_sync(0xffffffffu, mx, 1));
            mx = fmaxf(mx, __shfl_xor_sync(0xffffffffu, mx, 2));
            float sum = 0.f;
            #pragma unroll
            for (int j = 0; j < 16; j++) {
                float p = __expf(Srow[j] - mx);
                Srow[j] = tf32r(p);
                sum += p;
            }
            sum += __shfl_xor_sync(0xffffffffu, sum, 1);
            sum += __shfl_xor_sync(0xffffffffu, sum, 2);
            if (ssub == 0) {
                float alpha = __expf(mo - mx);
                a_s[srow] = alpha;
                l_s[srow] = l_s[srow] * alpha + sum;
                m_s[srow] = mx;
            }
        }
        __syncthreads();

        // Rescale output accumulator
        #pragma unroll
        for (int mi = 0; mi < 2; mi++) {
            int rb = wy * 32 + mi * 16 + t4;
            float al0 = a_s[rb];
            float al1 = a_s[rb + 8];
            #pragma unroll
            for (int ni = 0; ni < 4; ni++) {
                o[mi][ni][0] *= al0; o[mi][ni][1] *= al0;
                o[mi][ni][2] *= al1; o[mi][ni][3] *= al1;
            }
        }

        // O += P @ V  (warp tile 32x32)
        #pragma unroll
        for (int ks = 0; ks < FA_BC; ks += 8) {
            float afr[2][4], bfr[4][2];
            #pragma unroll
            for (int mi = 0; mi < 2; mi++) {
                int rb = wy * 32 + mi * 16;
                afr[mi][0] = Ss[(rb + t4) * S_ST + ks + tm4];
                afr[mi][1] = Ss[(rb + 8 + t4) * S_ST + ks + tm4];
                afr[mi][2] = Ss[(rb + t4) * S_ST + ks + tm4 + 4];
                afr[mi][3] = Ss[(rb + 8 + t4) * S_ST + ks + tm4 + 4];
            }
            #pragma unroll
            for (int ni = 0; ni < 4; ni++) {
                int cb = wx * 32 + ni * 8;
                bfr[ni][0] = Vs[(ks + tm4) * V_ST + cb + t4];
                bfr[ni][1] = Vs[(ks + tm4 + 4) * V_ST + cb + t4];
            }
            #pragma unroll
            for (int mi = 0; mi < 2; mi++)
                #pragma unroll
                for (int ni = 0; ni < 4; ni++)
                    mma_tf32(o[mi][ni], afr[mi], bfr[ni]);
        }
        __syncthreads();
    }

    // Epilogue: divide by l, write y (B,T,H,D)
    float* ybase = y + (size_t)b * T_ * C_ + h * D_;
    #pragma unroll
    for (int mi = 0; mi < 2; mi++) {
        int rb = wy * 32 + mi * 16 + t4;
        float inv0 = 1.f / l_s[rb];
        float inv1 = 1.f / l_s[rb + 8];
        #pragma unroll
        for (int ni = 0; ni < 4; ni++) {
            int col = wx * 32 + ni * 8 + tm4 * 2;
            float* d0 = ybase + (size_t)(q0 + rb) * C_ + col;
            float* d1 = ybase + (size_t)(q0 + rb + 8) * C_ + col;
            *(float2*)d0 = make_float2(o[mi][ni][0] * inv0, o[mi][ni][1] * inv0);
            *(float2*)d1 = make_float2(o[mi][ni][2] * inv1, o[mi][ni][3] * inv1);
        }
    }
}

// ---------------------------------------------------------------------------
// Launch
// ---------------------------------------------------------------------------
extern "C" void kernel_launch(void* const* d_in, const int* in_sizes, int n_in,
                              void* d_out, int out_size)
{
    const float* x   = (const float*)d_in[0];
    const float* cs  = (const float*)d_in[1];
    const float* sn  = (const float*)d_in[2];
    const float* Wq  = (const float*)d_in[3];
    const float* Wk  = (const float*)d_in[4];
    const float* Wv  = (const float*)d_in[5];
    const float* Wo  = (const float*)d_in[6];
    float* out = (float*)d_out;

    float *qp, *kp, *vp, *yp;
    cudaGetSymbolAddress((void**)&qp, g_q);
    cudaGetSymbolAddress((void**)&kp, g_k);
    cudaGetSymbolAddress((void**)&vp, g_v);
    cudaGetSymbolAddress((void**)&yp, g_y);

    const int fa_smem = FA_SMEM_FLOATS * 4;
    cudaFuncSetAttribute(flash_attn_tf32, cudaFuncAttributeMaxDynamicSharedMemorySize, fa_smem);

    dim3 blk256(256);
    // Projections
    gemm_tf32<<<dim3(C_ / GBN, M_ / GBM), blk256>>>(x, Wq, qp, M_, C_, C_);
    gemm_tf32<<<dim3(KVC_ / GBN, M_ / GBM), blk256>>>(x, Wk, kp, M_, KVC_, C_);
    gemm_tf32<<<dim3(KVC_ / GBN, M_ / GBM), blk256>>>(x, Wv, vp, M_, KVC_, C_);
    // RoPE + RMSNorm
    rope_rms_kernel<<<M_ * H_, 128>>>(qp, cs, sn, H_);
    rope_rms_kernel<<<M_ * KVH_, 128>>>(kp, cs, sn, KVH_);
    // Attention
    flash_attn_tf32<<<dim3(T_ / FA_BR, B_ * H_), blk256, fa_smem>>>(qp, kp, vp, yp);
    // Output projection
    gemm_tf32<<<dim3(C_ / GBN, M_ / GBM), blk256>>>(yp, Wo, out, M_, C_, C_);
}

// round 6
// speedup vs baseline: 3.6674x; 1.1932x over previous
#include <cuda_runtime.h>
#include <cuda_bf16.h>
#include <math.h>
#include <stdint.h>

// Problem constants
#define B_ 2
#define T_ 2048
#define C_ 2048
#define H_ 16
#define KVH_ 4
#define D_ 128
#define M_ (B_ * T_)          // 4096
#define KVC_ (KVH_ * D_)      // 512
#define SCALE_ 0.08838834764831845f
#define RMS_EPS 1.1920929e-07f

// ---------------------------------------------------------------------------
// Scratch (device globals; no allocation allowed)
// ---------------------------------------------------------------------------
__device__ float g_q[(size_t)M_ * C_];    // 32 MiB
__device__ float g_k[(size_t)M_ * KVC_];  // 8 MiB
__device__ float g_v[(size_t)M_ * KVC_];  // 8 MiB
__device__ float g_y[(size_t)M_ * C_];    // 32 MiB

// ---------------------------------------------------------------------------
// tf32 helpers
// ---------------------------------------------------------------------------
__device__ __forceinline__ float tf32r(float x) {
    unsigned u;
    asm("cvt.rna.tf32.f32 %0, %1;" : "=r"(u) : "f"(x));
    return __uint_as_float(u);
}

__device__ __forceinline__ void mma_tf32(float* c, const float* a, const float* b) {
    const unsigned* A = reinterpret_cast<const unsigned*>(a);
    const unsigned* Bv = reinterpret_cast<const unsigned*>(b);
    asm volatile(
        "mma.sync.aligned.m16n8k8.row.col.f32.tf32.tf32.f32 "
        "{%0,%1,%2,%3}, {%4,%5,%6,%7}, {%8,%9}, {%0,%1,%2,%3};\n"
        : "+f"(c[0]), "+f"(c[1]), "+f"(c[2]), "+f"(c[3])
        : "r"(A[0]), "r"(A[1]), "r"(A[2]), "r"(A[3]), "r"(Bv[0]), "r"(Bv[1]));
}

// ---------------------------------------------------------------------------
// Pipelined tf32 GEMM mainloop (128x128 tile, K-step 32, 256 threads).
// Register-prefetch next K-tile during compute; double-buffered smem.
// ---------------------------------------------------------------------------
#define A_ST 36      // As row stride: bank = 4r+c, conflict-free
#define B_ST 136     // Bs row stride: bank = 8r+c, conflict-free
#define ABUF (128 * A_ST)                   // 4608 floats
#define BBUF (32 * B_ST)                    // 4352 floats
#define GEMM_SM_FLOATS (2 * ABUF + 2 * BBUF)  // 17920 floats = 71680 B
#define STAGE_ST 132

__device__ __forceinline__ void gemm_main(
    const float* __restrict__ Ab,   // A block base (row stride K)
    const float* __restrict__ Bb,   // B block base (row stride Nb), pre-offset to col tile
    int Nb, int K, float* sm, float acc[4][4][4])
{
    float* As = sm;
    float* Bs = sm + 2 * ABUF;
    const int tid = threadIdx.x;
    const int lane = tid & 31;
    const int wid = tid >> 5;
    const int t4 = lane >> 2;
    const int tm4 = lane & 3;
    const int wy = wid & 1;
    const int wx = wid >> 1;

    #pragma unroll
    for (int i = 0; i < 4; i++)
        #pragma unroll
        for (int j = 0; j < 4; j++)
            #pragma unroll
            for (int r = 0; r < 4; r++) acc[i][j][r] = 0.f;

    const int NT = K >> 5;
    float4 pa[4], pb[4];

    // Prologue: load K-tile 0
    #pragma unroll
    for (int i = 0; i < 4; i++) {
        int idx = tid + i * 256;
        int r = idx >> 3, cg = idx & 7;
        pa[i] = *(const float4*)(Ab + (size_t)r * K + cg * 4);
    }
    #pragma unroll
    for (int i = 0; i < 4; i++) {
        int idx = tid + i * 256;
        int r = idx >> 5, c = (idx & 31) << 2;
        pb[i] = *(const float4*)(Bb + (size_t)r * Nb + c);
    }
    #pragma unroll
    for (int i = 0; i < 4; i++) {
        int idx = tid + i * 256;
        int r = idx >> 3, cg = idx & 7;
        float* d = &As[r * A_ST + cg * 4];
        d[0] = tf32r(pa[i].x); d[1] = tf32r(pa[i].y); d[2] = tf32r(pa[i].z); d[3] = tf32r(pa[i].w);
    }
    #pragma unroll
    for (int i = 0; i < 4; i++) {
        int idx = tid + i * 256;
        int r = idx >> 5, c = (idx & 31) << 2;
        float* d = &Bs[r * B_ST + c];
        d[0] = tf32r(pb[i].x); d[1] = tf32r(pb[i].y); d[2] = tf32r(pb[i].z); d[3] = tf32r(pb[i].w);
    }
    __syncthreads();

    for (int t = 0; t < NT; t++) {
        const int s = t & 1;
        // Prefetch next K-tile into registers (latency hidden by compute below)
        if (t + 1 < NT) {
            const float* An = Ab + (t + 1) * 32;
            const float* Bn = Bb + (size_t)((t + 1) * 32) * Nb;
            #pragma unroll
            for (int i = 0; i < 4; i++) {
                int idx = tid + i * 256;
                int r = idx >> 3, cg = idx & 7;
                pa[i] = *(const float4*)(An + (size_t)r * K + cg * 4);
            }
            #pragma unroll
            for (int i = 0; i < 4; i++) {
                int idx = tid + i * 256;
                int r = idx >> 5, c = (idx & 31) << 2;
                pb[i] = *(const float4*)(Bn + (size_t)r * Nb + c);
            }
        }

        float* Asb = As + s * ABUF;
        float* Bsb = Bs + s * BBUF;
        #pragma unroll
        for (int ks = 0; ks < 32; ks += 8) {
            float afr[4][4], bfr[4][2];
            #pragma unroll
            for (int mi = 0; mi < 4; mi++) {
                int rb = wy * 64 + mi * 16;
                afr[mi][0] = Asb[(rb + t4) * A_ST + ks + tm4];
                afr[mi][1] = Asb[(rb + 8 + t4) * A_ST + ks + tm4];
                afr[mi][2] = Asb[(rb + t4) * A_ST + ks + tm4 + 4];
                afr[mi][3] = Asb[(rb + 8 + t4) * A_ST + ks + tm4 + 4];
            }
            #pragma unroll
            for (int ni = 0; ni < 4; ni++) {
                int cb = wx * 32 + ni * 8;
                bfr[ni][0] = Bsb[(ks + tm4) * B_ST + cb + t4];
                bfr[ni][1] = Bsb[(ks + tm4 + 4) * B_ST + cb + t4];
            }
            #pragma unroll
            for (int mi = 0; mi < 4; mi++)
                #pragma unroll
                for (int ni = 0; ni < 4; ni++)
                    mma_tf32(acc[mi][ni], afr[mi], bfr[ni]);
        }

        if (t + 1 < NT) {
            float* Ad = As + (s ^ 1) * ABUF;
            float* Bd = Bs + (s ^ 1) * BBUF;
            #pragma unroll
            for (int i = 0; i < 4; i++) {
                int idx = tid + i * 256;
                int r = idx >> 3, cg = idx & 7;
                float* d = &Ad[r * A_ST + cg * 4];
                d[0] = tf32r(pa[i].x); d[1] = tf32r(pa[i].y); d[2] = tf32r(pa[i].z); d[3] = tf32r(pa[i].w);
            }
            #pragma unroll
            for (int i = 0; i < 4; i++) {
                int idx = tid + i * 256;
                int r = idx >> 5, c = (idx & 31) << 2;
                float* d = &Bd[r * B_ST + c];
                d[0] = tf32r(pb[i].x); d[1] = tf32r(pb[i].y); d[2] = tf32r(pb[i].z); d[3] = tf32r(pb[i].w);
            }
            __syncthreads();
        }
    }
}

// Plain epilogue: write acc tile to out (pre-offset to tile origin), row stride Nout.
__device__ __forceinline__ void epi_plain(float acc[4][4][4], float* out, int Nout)
{
    const int tid = threadIdx.x;
    const int lane = tid & 31;
    const int wid = tid >> 5;
    const int t4 = lane >> 2;
    const int tm4 = lane & 3;
    const int wy = wid & 1;
    const int wx = wid >> 1;
    #pragma unroll
    for (int mi = 0; mi < 4; mi++) {
        int row = wy * 64 + mi * 16 + t4;
        #pragma unroll
        for (int ni = 0; ni < 4; ni++) {
            int col = wx * 32 + ni * 8 + tm4 * 2;
            *(float2*)(out + (size_t)row * Nout + col) = make_float2(acc[mi][ni][0], acc[mi][ni][1]);
            *(float2*)(out + (size_t)(row + 8) * Nout + col) = make_float2(acc[mi][ni][2], acc[mi][ni][3]);
        }
    }
}

// RoPE + RMSNorm epilogue: stage tile in smem, transform, coalesced write.
// Tile = 128 rows x 128 cols = exactly one head's full dim.
__device__ __forceinline__ void epi_rope(
    float acc[4][4][4], float* sm,
    const float* __restrict__ cs, const float* __restrict__ sn,
    float* out, int Nout, int m0)
{
    float* stage = sm;   // 128 x STAGE_ST floats (reuses gemm buffers; <= 71680B)
    const int tid = threadIdx.x;
    const int lane = tid & 31;
    const int wid = tid >> 5;
    const int t4 = lane >> 2;
    const int tm4 = lane & 3;
    const int wy = wid & 1;
    const int wx = wid >> 1;

    __syncthreads();   // gemm buffers fully consumed before reuse
    #pragma unroll
    for (int mi = 0; mi < 4; mi++) {
        int row = wy * 64 + mi * 16 + t4;
        #pragma unroll
        for (int ni = 0; ni < 4; ni++) {
            int col = wx * 32 + ni * 8 + tm4 * 2;
            *(float2*)(&stage[row * STAGE_ST + col]) = make_float2(acc[mi][ni][0], acc[mi][ni][1]);
            *(float2*)(&stage[(row + 8) * STAGE_ST + col]) = make_float2(acc[mi][ni][2], acc[mi][ni][3]);
        }
    }
    __syncthreads();

    // 2 threads per row: hf=0 -> cols [0,64), hf=1 -> cols [64,128)
    {
        const int r = tid >> 1;
        const int hf = tid & 1;
        const int tpos = (m0 + r) & (T_ - 1);
        const float* cr = cs + tpos * 64;
        const float* sr = sn + tpos * 64;
        float* row = &stage[r * STAGE_ST];

        // Pass 1: sum of squares of post-rope values
        float ss = 0.f;
        #pragma unroll 8
        for (int j = 0; j < 64; j++) {
            float x1 = row[j], x2 = row[j + 64];
            float c = cr[j], s = sr[j];
            float val = hf ? (x2 * c - x1 * s) : (x1 * c + x2 * s);
            ss += val * val;
        }
        ss += __shfl_xor_sync(0xffffffffu, ss, 1);
        float inv = rsqrtf(ss * (1.f / 128.f) + RMS_EPS);

        // Pass 2: recompute and overwrite own half (warp-synchronous after shfl)
        #pragma unroll 8
        for (int j = 0; j < 64; j++) {
            float x1 = row[j], x2 = row[j + 64];
            float c = cr[j], s = sr[j];
            float val = hf ? (x2 * c - x1 * s) : (x1 * c + x2 * s);
            row[hf * 64 + j] = val * inv;
        }
    }
    __syncthreads();

    // Coalesced write: warp covers one full row of 128 floats
    {
        const int c4 = (lane) * 4;
        const int rb = tid >> 5;
        #pragma unroll
        for (int p = 0; p < 16; p++) {
            int row = p * 8 + rb;
            float4 v = *(const float4*)(&stage[row * STAGE_ST + c4]);
            *(float4*)(out + (size_t)row * Nout + c4) = v;
        }
    }
}

// ---------------------------------------------------------------------------
// Fused QKV projection + RoPE + RMSNorm.
// grid (24, 32): bx 0-15 -> Q (rope), 16-19 -> K (rope), 20-23 -> V (plain).
// ---------------------------------------------------------------------------
__global__ __launch_bounds__(256, 1) void gemm_qkv(
    const float* __restrict__ x,
    const float* __restrict__ Wq, const float* __restrict__ Wk, const float* __restrict__ Wv,
    const float* __restrict__ cs, const float* __restrict__ sn,
    float* __restrict__ q, float* __restrict__ k, float* __restrict__ v)
{
    extern __shared__ float sm[];
    const int bx = blockIdx.x;
    const int m0 = blockIdx.y * 128;

    const float* Bw;
    float* outp;
    int Nb, colt;
    bool dorope;
    if (bx < 16)      { Bw = Wq; outp = q; Nb = C_;   colt = bx * 128;        dorope = true; }
    else if (bx < 20) { Bw = Wk; outp = k; Nb = KVC_; colt = (bx - 16) * 128; dorope = true; }
    else              { Bw = Wv; outp = v; Nb = KVC_; colt = (bx - 20) * 128; dorope = false; }

    float acc[4][4][4];
    gemm_main(x + (size_t)m0 * C_, Bw + colt, Nb, C_, sm, acc);

    float* out_tile = outp + (size_t)m0 * Nb + colt;
    if (dorope) epi_rope(acc, sm, cs, sn, out_tile, Nb, m0);
    else        epi_plain(acc, out_tile, Nb);
}

// ---------------------------------------------------------------------------
// Output projection: out = y @ Wo. grid (16, 32).
// ---------------------------------------------------------------------------
__global__ __launch_bounds__(256, 1) void gemm_out(
    const float* __restrict__ y, const float* __restrict__ Wo, float* __restrict__ out)
{
    extern __shared__ float sm[];
    const int m0 = blockIdx.y * 128;
    const int colt = blockIdx.x * 128;
    float acc[4][4][4];
    gemm_main(y + (size_t)m0 * C_, Wo + colt, C_, C_, sm, acc);
    epi_plain(acc, out + (size_t)m0 * C_ + colt, C_);
}

// ---------------------------------------------------------------------------
// Flash attention (causal, GQA rep=4), tf32 mma, fp32 accum.
// Reversed q-tile order: longest-running CTAs launch first.
// ---------------------------------------------------------------------------
#define FA_BR 64
#define FA_BC 64
#define Q_ST 132
#define K_ST 132
#define V_ST 136
#define S_ST 68

#define FA_SMEM_FLOATS (FA_BR * Q_ST + FA_BC * K_ST + FA_BC * V_ST + FA_BR * S_ST + 3 * FA_BR)

__global__ __launch_bounds__(256, 1) void flash_attn_tf32(
    const float* __restrict__ q, const float* __restrict__ k,
    const float* __restrict__ v, float* __restrict__ y)
{
    extern __shared__ float sm[];
    float* Qs = sm;
    float* Ks = Qs + FA_BR * Q_ST;
    float* Vs = Ks + FA_BC * K_ST;
    float* Ss = Vs + FA_BC * V_ST;
    float* m_s = Ss + FA_BR * S_ST;
    float* l_s = m_s + FA_BR;
    float* a_s = l_s + FA_BR;

    const int tid = threadIdx.x;
    const int lane = tid & 31;
    const int wid = tid >> 5;
    const int t4 = lane >> 2;
    const int tm4 = lane & 3;
    const int wy = wid & 1;
    const int wx = wid >> 1;

    const int bh = blockIdx.y;
    const int b = bh >> 4;
    const int h = bh & 15;
    const int kvh = h >> 2;
    const int qt = gridDim.x - 1 - blockIdx.x;   // reversed: long CTAs first
    const int q0 = qt * FA_BR;

    const float* qbase = q + (size_t)b * T_ * C_ + h * D_;
    const float* kbase = k + (size_t)b * T_ * KVC_ + kvh * D_;
    const float* vbase = v + (size_t)b * T_ * KVC_ + kvh * D_;

    #pragma unroll
    for (int i = 0; i < 8; i++) {
        int idx = tid + i * 256;
        int r = idx >> 5;
        int c = (idx & 31) << 2;
        float4 vv = *(const float4*)(qbase + (size_t)(q0 + r) * C_ + c);
        float* d = &Qs[r * Q_ST + c];
        d[0] = tf32r(vv.x); d[1] = tf32r(vv.y); d[2] = tf32r(vv.z); d[3] = tf32r(vv.w);
    }
    if (tid < FA_BR) { m_s[tid] = -INFINITY; l_s[tid] = 0.f; }

    float o[2][4][4];
    #pragma unroll
    for (int i = 0; i < 2; i++)
        #pragma unroll
        for (int j = 0; j < 4; j++)
            #pragma unroll
            for (int r = 0; r < 4; r++) o[i][j][r] = 0.f;
    __syncthreads();

    for (int kt = 0; kt <= qt; kt++) {
        const int k0 = kt * FA_BC;
        #pragma unroll
        for (int i = 0; i < 8; i++) {
            int idx = tid + i * 256;
            int r = idx >> 5;
            int c = (idx & 31) << 2;
            float4 kv = *(const float4*)(kbase + (size_t)(k0 + r) * KVC_ + c);
            float* dk = &Ks[r * K_ST + c];
            dk[0] = tf32r(kv.x); dk[1] = tf32r(kv.y); dk[2] = tf32r(kv.z); dk[3] = tf32r(kv.w);
            float4 vv = *(const float4*)(vbase + (size_t)(k0 + r) * KVC_ + c);
            float* dv = &Vs[r * V_ST + c];
            dv[0] = tf32r(vv.x); dv[1] = tf32r(vv.y); dv[2] = tf32r(vv.z); dv[3] = tf32r(vv.w);
        }
        __syncthreads();

        float sacc[2][2][4];
        #pragma unroll
        for (int i = 0; i < 2; i++)
            #pragma unroll
            for (int j = 0; j < 2; j++)
                #pragma unroll
                for (int r = 0; r < 4; r++) sacc[i][j][r] = 0.f;

        #pragma unroll
        for (int ks = 0; ks < D_; ks += 8) {
            float afr[2][4], bfr[2][2];
            #pragma unroll
            for (int mi = 0; mi < 2; mi++) {
                int rb = wy * 32 + mi * 16;
                afr[mi][0] = Qs[(rb + t4) * Q_ST + ks + tm4];
                afr[mi][1] = Qs[(rb + 8 + t4) * Q_ST + ks + tm4];
                afr[mi][2] = Qs[(rb + t4) * Q_ST + ks + tm4 + 4];
                afr[mi][3] = Qs[(rb + 8 + t4) * Q_ST + ks + tm4 + 4];
            }
            #pragma unroll
            for (int ni = 0; ni < 2; ni++) {
                int cb = wx * 16 + ni * 8;
                bfr[ni][0] = Ks[(cb + t4) * K_ST + ks + tm4];
                bfr[ni][1] = Ks[(cb + t4) * K_ST + ks + tm4 + 4];
            }
            #pragma unroll
            for (int mi = 0; mi < 2; mi++)
                #pragma unroll
                for (int ni = 0; ni < 2; ni++)
                    mma_tf32(sacc[mi][ni], afr[mi], bfr[ni]);
        }

        const bool diag = (kt == qt);
        #pragma unroll
        for (int mi = 0; mi < 2; mi++) {
            #pragma unroll
            for (int ni = 0; ni < 2; ni++) {
                int rA = wy * 32 + mi * 16 + t4;
                int cA = wx * 16 + ni * 8 + tm4 * 2;
                #pragma unroll
                for (int half = 0; half < 2; half++) {
                    int r = rA + half * 8;
                    float v0 = sacc[mi][ni][half * 2 + 0] * SCALE_;
                    float v1 = sacc[mi][ni][half * 2 + 1] * SCALE_;
                    if (diag) {
                        if (cA > r) v0 = -INFINITY;
                        if (cA + 1 > r) v1 = -INFINITY;
                    }
                    *(float2*)(&Ss[r * S_ST + cA]) = make_float2(v0, v1);
                }
            }
        }
        __syncthreads();

        {
            const int srow = tid >> 2;
            const int ssub = tid & 3;
            float* Srow = Ss + srow * S_ST + ssub * 16;
            float mo = m_s[srow];
            float mx = mo;
            #pragma unroll
            for (int j = 0; j < 16; j++) mx = fmaxf(mx, Srow[j]);
            mx = fmaxf(mx, __shfl_xor_sync(0xffffffffu, mx, 1));
            mx = fmaxf(mx, __shfl_xor_sync(0xffffffffu, mx, 2));
            float sum = 0.f;
            #pragma unroll
            for (int j = 0; j < 16; j++) {
                float p = __expf(Srow[j] - mx);
                Srow[j] = tf32r(p);
                sum += p;
            }
            sum += __shfl_xor_sync(0xffffffffu, sum, 1);
            sum += __shfl_xor_sync(0xffffffffu, sum, 2);
            if (ssub == 0) {
                float alpha = __expf(mo - mx);
                a_s[srow] = alpha;
                l_s[srow] = l_s[srow] * alpha + sum;
                m_s[srow] = mx;
            }
        }
        __syncthreads();

        #pragma unroll
        for (int mi = 0; mi < 2; mi++) {
            int rb = wy * 32 + mi * 16 + t4;
            float al0 = a_s[rb];
            float al1 = a_s[rb + 8];
            #pragma unroll
            for (int ni = 0; ni < 4; ni++) {
                o[mi][ni][0] *= al0; o[mi][ni][1] *= al0;
                o[mi][ni][2] *= al1; o[mi][ni][3] *= al1;
            }
        }

        #pragma unroll
        for (int ks = 0; ks < FA_BC; ks += 8) {
            float afr[2][4], bfr[4][2];
            #pragma unroll
            for (int mi = 0; mi < 2; mi++) {
                int rb = wy * 32 + mi * 16;
                afr[mi][0] = Ss[(rb + t4) * S_ST + ks + tm4];
                afr[mi][1] = Ss[(rb + 8 + t4) * S_ST + ks + tm4];
                afr[mi][2] = Ss[(rb + t4) * S_ST + ks + tm4 + 4];
                afr[mi][3] = Ss[(rb + 8 + t4) * S_ST + ks + tm4 + 4];
            }
            #pragma unroll
            for (int ni = 0; ni < 4; ni++) {
                int cb = wx * 32 + ni * 8;
                bfr[ni][0] = Vs[(ks + tm4) * V_ST + cb + t4];
                bfr[ni][1] = Vs[(ks + tm4 + 4) * V_ST + cb + t4];
            }
            #pragma unroll
            for (int mi = 0; mi < 2; mi++)
                #pragma unroll
                for (int ni = 0; ni < 4; ni++)
                    mma_tf32(o[mi][ni], afr[mi], bfr[ni]);
        }
        __syncthreads();
    }

    float* ybase = y + (size_t)b * T_ * C_ + h * D_;
    #pragma unroll
    for (int mi = 0; mi < 2; mi++) {
        int rb = wy * 32 + mi * 16 + t4;
        float inv0 = 1.f / l_s[rb];
        float inv1 = 1.f / l_s[rb + 8];
        #pragma unroll
        for (int ni = 0; ni < 4; ni++) {
            int col = wx * 32 + ni * 8 + tm4 * 2;
            float* d0 = ybase + (size_t)(q0 + rb) * C_ + col;
            float* d1 = ybase + (size_t)(q0 + rb + 8) * C_ + col;
            *(float2*)d0 = make_float2(o[mi][ni][0] * inv0, o[mi][ni][1] * inv0);
            *(float2*)d1 = make_float2(o[mi][ni][2] * inv1, o[mi][ni][3] * inv1);
        }
    }
}

// ---------------------------------------------------------------------------
// Launch
// ---------------------------------------------------------------------------
extern "C" void kernel_launch(void* const* d_in, const int* in_sizes, int n_in,
                              void* d_out, int out_size)
{
    const float* x   = (const float*)d_in[0];
    const float* cs  = (const float*)d_in[1];
    const float* sn  = (const float*)d_in[2];
    const float* Wq  = (const float*)d_in[3];
    const float* Wk  = (const float*)d_in[4];
    const float* Wv  = (const float*)d_in[5];
    const float* Wo  = (const float*)d_in[6];
    float* out = (float*)d_out;

    float *qp, *kp, *vp, *yp;
    cudaGetSymbolAddress((void**)&qp, g_q);
    cudaGetSymbolAddress((void**)&kp, g_k);
    cudaGetSymbolAddress((void**)&vp, g_v);
    cudaGetSymbolAddress((void**)&yp, g_y);

    const int gemm_smem = GEMM_SM_FLOATS * 4;   // 71680 B
    cudaFuncSetAttribute(gemm_qkv, cudaFuncAttributeMaxDynamicSharedMemorySize, gemm_smem);
    cudaFuncSetAttribute(gemm_out, cudaFuncAttributeMaxDynamicSharedMemorySize, gemm_smem);
    const int fa_smem = FA_SMEM_FLOATS * 4;
    cudaFuncSetAttribute(flash_attn_tf32, cudaFuncAttributeMaxDynamicSharedMemorySize, fa_smem);

    dim3 blk256(256);
    // Fused Q/K/V projections + RoPE + RMSNorm
    gemm_qkv<<<dim3(24, M_ / 128), blk256, gemm_smem>>>(x, Wq, Wk, Wv, cs, sn, qp, kp, vp);
    // Attention
    flash_attn_tf32<<<dim3(T_ / FA_BR, B_ * H_), blk256, fa_smem>>>(qp, kp, vp, yp);
    // Output projection
    gemm_out<<<dim3(C_ / 128, M_ / 128), blk256, gemm_smem>>>(yp, Wo, out);
}

// round 9
// speedup vs baseline: 3.9387x; 1.0740x over previous
#include <cuda_runtime.h>
#include <cuda_bf16.h>
#include <math.h>
#include <stdint.h>

// Problem constants
#define B_ 2
#define T_ 2048
#define C_ 2048
#define H_ 16
#define KVH_ 4
#define D_ 128
#define M_ (B_ * T_)          // 4096
#define KVC_ (KVH_ * D_)      // 512
#define SCALE_ 0.08838834764831845f
#define RMS_EPS 1.1920929e-07f

// ---------------------------------------------------------------------------
// Scratch (device globals; no allocation allowed)
// ---------------------------------------------------------------------------
__device__ float g_q[(size_t)M_ * C_];     // 32 MiB (rope+rms'd Q, tf32)
__device__ float g_k[(size_t)M_ * KVC_];   // 8 MiB
__device__ float g_v[(size_t)M_ * KVC_];   // 8 MiB
__device__ float g_y[(size_t)M_ * C_];     // 32 MiB
__device__ float g_x[(size_t)M_ * C_];     // 32 MiB (tf32-rounded x)
__device__ float g_wq[(size_t)C_ * C_];    // 16 MiB
__device__ float g_wk[(size_t)C_ * KVC_];  // 4 MiB
__device__ float g_wv[(size_t)C_ * KVC_];  // 4 MiB
__device__ float g_wo[(size_t)C_ * C_];    // 16 MiB

// ---------------------------------------------------------------------------
// helpers
// ---------------------------------------------------------------------------
__device__ __forceinline__ uint32_t smem_u32(const void* p) {
    uint32_t a;
    asm("{ .reg .u64 t; cvta.to.shared.u64 t, %1; cvt.u32.u64 %0, t; }" : "=r"(a) : "l"(p));
    return a;
}

__device__ __forceinline__ float tf32r(float x) {
    unsigned u;
    asm("cvt.rna.tf32.f32 %0, %1;" : "=r"(u) : "f"(x));
    return __uint_as_float(u);
}

__device__ __forceinline__ void cp16(uint32_t s, const void* g) {
    asm volatile("cp.async.cg.shared.global [%0], [%1], 16;" :: "r"(s), "l"(g) : "memory");
}
#define CP_COMMIT() asm volatile("cp.async.commit_group;" ::: "memory")
#define CP_WAIT(n)  asm volatile("cp.async.wait_group %0;" :: "n"(n) : "memory")

__device__ __forceinline__ void mma_tf32(float* c, const float* a, const float* b) {
    const unsigned* A = reinterpret_cast<const unsigned*>(a);
    const unsigned* Bv = reinterpret_cast<const unsigned*>(b);
    asm volatile(
        "mma.sync.aligned.m16n8k8.row.col.f32.tf32.tf32.f32 "
        "{%0,%1,%2,%3}, {%4,%5,%6,%7}, {%8,%9}, {%0,%1,%2,%3};\n"
        : "+f"(c[0]), "+f"(c[1]), "+f"(c[2]), "+f"(c[3])
        : "r"(A[0]), "r"(A[1]), "r"(A[2]), "r"(A[3]), "r"(Bv[0]), "r"(Bv[1]));
}

// ---------------------------------------------------------------------------
// tf32 pre-round kernel (elementwise, float4)
// ---------------------------------------------------------------------------
__global__ __launch_bounds__(256) void tf32_round_kernel(
    const float4* __restrict__ src, float4* __restrict__ dst, int n4)
{
    int i = blockIdx.x * 256 + threadIdx.x;
    if (i < n4) {
        float4 v = src[i];
        dst[i] = make_float4(tf32r(v.x), tf32r(v.y), tf32r(v.z), tf32r(v.w));
    }
}

// ---------------------------------------------------------------------------
// cp.async 4-stage pipelined tf32 GEMM mainloop.
// Tile 128x128, K-step 32, 256 threads (8 warps 2x4), warp tile 64x32.
// Inputs MUST already be tf32-rounded.
// ---------------------------------------------------------------------------
#define A_ST 36
#define B_ST 136
#define ABUF (128 * A_ST)      // 4608 floats
#define BBUF (32 * B_ST)       // 4352 floats
#define STAGES 4
#define GEMM_SM_FLOATS (STAGES * (ABUF + BBUF))   // 35840 floats = 143360 B
#define STAGE_ST 132

__device__ __forceinline__ void gemm_main(
    const float* __restrict__ Ab, const float* __restrict__ Bb,
    int Nb, int K, float* sm, float acc[4][4][4])
{
    float* As = sm;
    float* Bs = sm + STAGES * ABUF;
    const uint32_t sA = smem_u32(As);
    const uint32_t sB = smem_u32(Bs);

    const int tid = threadIdx.x;
    const int lane = tid & 31;
    const int wid = tid >> 5;
    const int t4 = lane >> 2;
    const int tm4 = lane & 3;
    const int wy = wid & 1;
    const int wx = wid >> 1;

    #pragma unroll
    for (int i = 0; i < 4; i++)
        #pragma unroll
        for (int j = 0; j < 4; j++)
            #pragma unroll
            for (int r = 0; r < 4; r++) acc[i][j][r] = 0.f;

    const int NT = K >> 5;

    // per-thread load coords
    const int ar = tid >> 3;            // +32 per i (4 iters covers 128 rows? no:)
    // A: 128 rows x 8 chunks -> idx = tid + i*256; r=idx>>3, c=(idx&7)*4
    // B: 32 rows x 32 chunks -> r=idx>>5, c=(idx&31)*4
    (void)ar;

    auto load_stage = [&](int t, int slot) {
        const float* An = Ab + t * 32;
        const float* Bn = Bb + (size_t)(t * 32) * Nb;
        #pragma unroll
        for (int i = 0; i < 4; i++) {
            int idx = tid + i * 256;
            int r = idx >> 3, cg = (idx & 7) << 2;
            cp16(sA + (uint32_t)(slot * ABUF + r * A_ST + cg) * 4,
                 An + (size_t)r * K + cg);
        }
        #pragma unroll
        for (int i = 0; i < 4; i++) {
            int idx = tid + i * 256;
            int r = idx >> 5, c = (idx & 31) << 2;
            cp16(sB + (uint32_t)(slot * BBUF + r * B_ST + c) * 4,
                 Bn + (size_t)r * Nb + c);
        }
    };

    // Prologue: stages 0..STAGES-2
    #pragma unroll
    for (int s = 0; s < STAGES - 1; s++) {
        if (s < NT) load_stage(s, s);
        CP_COMMIT();
    }

    for (int t = 0; t < NT; t++) {
        CP_WAIT(STAGES - 2);
        __syncthreads();

        int u = t + STAGES - 1;
        if (u < NT) load_stage(u, u & (STAGES - 1));
        CP_COMMIT();

        const int slot = t & (STAGES - 1);
        float* Asb = As + slot * ABUF;
        float* Bsb = Bs + slot * BBUF;
        #pragma unroll
        for (int ks = 0; ks < 32; ks += 8) {
            float afr[4][4], bfr[4][2];
            #pragma unroll
            for (int mi = 0; mi < 4; mi++) {
                int rb = wy * 64 + mi * 16;
                afr[mi][0] = Asb[(rb + t4) * A_ST + ks + tm4];
                afr[mi][1] = Asb[(rb + 8 + t4) * A_ST + ks + tm4];
                afr[mi][2] = Asb[(rb + t4) * A_ST + ks + tm4 + 4];
                afr[mi][3] = Asb[(rb + 8 + t4) * A_ST + ks + tm4 + 4];
            }
            #pragma unroll
            for (int ni = 0; ni < 4; ni++) {
                int cb = wx * 32 + ni * 8;
                bfr[ni][0] = Bsb[(ks + tm4) * B_ST + cb + t4];
                bfr[ni][1] = Bsb[(ks + tm4 + 4) * B_ST + cb + t4];
            }
            #pragma unroll
            for (int mi = 0; mi < 4; mi++)
                #pragma unroll
                for (int ni = 0; ni < 4; ni++)
                    mma_tf32(acc[mi][ni], afr[mi], bfr[ni]);
        }
    }
}

// Plain epilogue (optionally tf32-round for downstream tensor consumers)
template <bool ROUND>
__device__ __forceinline__ void epi_plain(float acc[4][4][4], float* out, int Nout)
{
    const int tid = threadIdx.x;
    const int lane = tid & 31;
    const int wid = tid >> 5;
    const int t4 = lane >> 2;
    const int tm4 = lane & 3;
    const int wy = wid & 1;
    const int wx = wid >> 1;
    #pragma unroll
    for (int mi = 0; mi < 4; mi++) {
        int row = wy * 64 + mi * 16 + t4;
        #pragma unroll
        for (int ni = 0; ni < 4; ni++) {
            int col = wx * 32 + ni * 8 + tm4 * 2;
            float a0 = acc[mi][ni][0], a1 = acc[mi][ni][1];
            float a2 = acc[mi][ni][2], a3 = acc[mi][ni][3];
            if (ROUND) { a0 = tf32r(a0); a1 = tf32r(a1); a2 = tf32r(a2); a3 = tf32r(a3); }
            *(float2*)(out + (size_t)row * Nout + col) = make_float2(a0, a1);
            *(float2*)(out + (size_t)(row + 8) * Nout + col) = make_float2(a2, a3);
        }
    }
}

// RoPE + RMSNorm epilogue (stores tf32-rounded)
__device__ __forceinline__ void epi_rope(
    float acc[4][4][4], float* sm,
    const float* __restrict__ cs, const float* __restrict__ sn,
    float* out, int Nout, int m0)
{
    float* stage = sm;
    const int tid = threadIdx.x;
    const int lane = tid & 31;
    const int wid = tid >> 5;
    const int t4 = lane >> 2;
    const int tm4 = lane & 3;
    const int wy = wid & 1;
    const int wx = wid >> 1;

    __syncthreads();
    #pragma unroll
    for (int mi = 0; mi < 4; mi++) {
        int row = wy * 64 + mi * 16 + t4;
        #pragma unroll
        for (int ni = 0; ni < 4; ni++) {
            int col = wx * 32 + ni * 8 + tm4 * 2;
            *(float2*)(&stage[row * STAGE_ST + col]) = make_float2(acc[mi][ni][0], acc[mi][ni][1]);
            *(float2*)(&stage[(row + 8) * STAGE_ST + col]) = make_float2(acc[mi][ni][2], acc[mi][ni][3]);
        }
    }
    __syncthreads();

    {
        const int r = tid >> 1;
        const int hf = tid & 1;
        const int tpos = (m0 + r) & (T_ - 1);
        const float* cr = cs + tpos * 64;
        const float* sr = sn + tpos * 64;
        float* row = &stage[r * STAGE_ST];

        float ss = 0.f;
        #pragma unroll 8
        for (int j = 0; j < 64; j++) {
            float x1 = row[j], x2 = row[j + 64];
            float c = cr[j], s = sr[j];
            float val = hf ? (x2 * c - x1 * s) : (x1 * c + x2 * s);
            ss += val * val;
        }
        ss += __shfl_xor_sync(0xffffffffu, ss, 1);
        float inv = rsqrtf(ss * (1.f / 128.f) + RMS_EPS);

        #pragma unroll 8
        for (int j = 0; j < 64; j++) {
            float x1 = row[j], x2 = row[j + 64];
            float c = cr[j], s = sr[j];
            float val = hf ? (x2 * c - x1 * s) : (x1 * c + x2 * s);
            row[hf * 64 + j] = tf32r(val * inv);
        }
    }
    __syncthreads();

    {
        const int c4 = lane * 4;
        const int rb = tid >> 5;
        #pragma unroll
        for (int p = 0; p < 16; p++) {
            int row = p * 8 + rb;
            float4 v = *(const float4*)(&stage[row * STAGE_ST + c4]);
            *(float4*)(out + (size_t)row * Nout + c4) = v;
        }
    }
}

// ---------------------------------------------------------------------------
// Fused QKV projection + RoPE + RMSNorm. grid (24, 32).
// ---------------------------------------------------------------------------
__global__ __launch_bounds__(256, 1) void gemm_qkv(
    const float* __restrict__ x,
    const float* __restrict__ Wq, const float* __restrict__ Wk, const float* __restrict__ Wv,
    const float* __restrict__ cs, const float* __restrict__ sn,
    float* __restrict__ q, float* __restrict__ k, float* __restrict__ v)
{
    extern __shared__ float sm[];
    const int bx = blockIdx.x;
    const int m0 = blockIdx.y * 128;

    const float* Bw;
    float* outp;
    int Nb, colt;
    bool dorope;
    if (bx < 16)      { Bw = Wq; outp = q; Nb = C_;   colt = bx * 128;        dorope = true; }
    else if (bx < 20) { Bw = Wk; outp = k; Nb = KVC_; colt = (bx - 16) * 128; dorope = true; }
    else              { Bw = Wv; outp = v; Nb = KVC_; colt = (bx - 20) * 128; dorope = false; }

    float acc[4][4][4];
    gemm_main(x + (size_t)m0 * C_, Bw + colt, Nb, C_, sm, acc);

    float* out_tile = outp + (size_t)m0 * Nb + colt;
    if (dorope) epi_rope(acc, sm, cs, sn, out_tile, Nb, m0);
    else        epi_plain<true>(acc, out_tile, Nb);
}

// ---------------------------------------------------------------------------
// Output projection: out = y @ Wo. grid (16, 32). No rounding on final out.
// ---------------------------------------------------------------------------
__global__ __launch_bounds__(256, 1) void gemm_out(
    const float* __restrict__ y, const float* __restrict__ Wo, float* __restrict__ out)
{
    extern __shared__ float sm[];
    const int m0 = blockIdx.y * 128;
    const int colt = blockIdx.x * 128;
    float acc[4][4][4];
    gemm_main(y + (size_t)m0 * C_, Wo + colt, C_, C_, sm, acc);
    epi_plain<false>(acc, out + (size_t)m0 * C_ + colt, C_);
}

// ---------------------------------------------------------------------------
// Flash attention (causal, GQA rep=4), tf32 mma, cp.async double-buffered K/V.
// Inputs q/k/v already tf32-rounded.
// ---------------------------------------------------------------------------
#define FA_BR 64
#define FA_BC 64
#define Q_ST 132
#define K_ST 132
#define V_ST 136
#define S_ST 68

// smem layout (floats)
#define SM_Q   0
#define SM_K   (FA_BR * Q_ST)                       // 8448
#define SM_V   (SM_K + 2 * FA_BC * K_ST)            // 8448 + 16896 = 25344
#define SM_S   (SM_V + 2 * FA_BC * V_ST)            // 25344 + 17408 = 42752
#define SM_M   (SM_S + FA_BR * S_ST)                // 47104
#define SM_L   (SM_M + FA_BR)
#define SM_A   (SM_L + FA_BR)
#define FA_SMEM_FLOATS (SM_A + FA_BR)               // 47296 floats = 189184 B

__global__ __launch_bounds__(256, 1) void flash_attn_tf32(
    const float* __restrict__ q, const float* __restrict__ k,
    const float* __restrict__ v, float* __restrict__ y)
{
    extern __shared__ float sm[];
    float* Qs = sm + SM_Q;
    float* Ks = sm + SM_K;
    float* Vs = sm + SM_V;
    float* Ss = sm + SM_S;
    float* m_s = sm + SM_M;
    float* l_s = sm + SM_L;
    float* a_s = sm + SM_A;
    const uint32_t sbase = smem_u32(sm);

    const int tid = threadIdx.x;
    const int lane = tid & 31;
    const int wid = tid >> 5;
    const int t4 = lane >> 2;
    const int tm4 = lane & 3;
    const int wy = wid & 1;
    const int wx = wid >> 1;

    const int bh = blockIdx.y;
    const int b = bh >> 4;
    const int h = bh & 15;
    const int kvh = h >> 2;
    const int qt = gridDim.x - 1 - blockIdx.x;   // reversed: long CTAs first
    const int q0 = qt * FA_BR;

    const float* qbase = q + (size_t)b * T_ * C_ + h * D_;
    const float* kbase = k + (size_t)b * T_ * KVC_ + kvh * D_;
    const float* vbase = v + (size_t)b * T_ * KVC_ + kvh * D_;

    auto issue_kv = [&](int kt, int slot) {
        const float* kb = kbase + (size_t)(kt * FA_BC) * KVC_;
        const float* vb = vbase + (size_t)(kt * FA_BC) * KVC_;
        #pragma unroll
        for (int i = 0; i < 8; i++) {
            int idx = tid + i * 256;
            int r = idx >> 5;
            int c = (idx & 31) << 2;
            cp16(sbase + (uint32_t)(SM_K + slot * FA_BC * K_ST + r * K_ST + c) * 4,
                 kb + (size_t)r * KVC_ + c);
            cp16(sbase + (uint32_t)(SM_V + slot * FA_BC * V_ST + r * V_ST + c) * 4,
                 vb + (size_t)r * KVC_ + c);
        }
    };

    // Prologue: Q + KV(0) in one group
    #pragma unroll
    for (int i = 0; i < 8; i++) {
        int idx = tid + i * 256;
        int r = idx >> 5;
        int c = (idx & 31) << 2;
        cp16(sbase + (uint32_t)(SM_Q + r * Q_ST + c) * 4,
             qbase + (size_t)(q0 + r) * C_ + c);
    }
    issue_kv(0, 0);
    CP_COMMIT();

    if (tid < FA_BR) { m_s[tid] = -INFINITY; l_s[tid] = 0.f; }

    float o[2][4][4];
    #pragma unroll
    for (int i = 0; i < 2; i++)
        #pragma unroll
        for (int j = 0; j < 4; j++)
            #pragma unroll
            for (int r = 0; r < 4; r++) o[i][j][r] = 0.f;

    for (int kt = 0; kt <= qt; kt++) {
        const int slot = kt & 1;
        CP_WAIT(0);
        __syncthreads();   // KV(kt) visible; all threads past PV(kt-1)

        if (kt < qt) { issue_kv(kt + 1, slot ^ 1); CP_COMMIT(); }

        float* Ksb = Ks + slot * FA_BC * K_ST;
        float* Vsb = Vs + slot * FA_BC * V_ST;

        // S = Q @ K^T
        float sacc[2][2][4];
        #pragma unroll
        for (int i = 0; i < 2; i++)
            #pragma unroll
            for (int j = 0; j < 2; j++)
                #pragma unroll
                for (int r = 0; r < 4; r++) sacc[i][j][r] = 0.f;

        #pragma unroll
        for (int ks = 0; ks < D_; ks += 8) {
            float afr[2][4], bfr[2][2];
            #pragma unroll
            for (int mi = 0; mi < 2; mi++) {
                int rb = wy * 32 + mi * 16;
                afr[mi][0] = Qs[(rb + t4) * Q_ST + ks + tm4];
                afr[mi][1] = Qs[(rb + 8 + t4) * Q_ST + ks + tm4];
                afr[mi][2] = Qs[(rb + t4) * Q_ST + ks + tm4 + 4];
                afr[mi][3] = Qs[(rb + 8 + t4) * Q_ST + ks + tm4 + 4];
            }
            #pragma unroll
            for (int ni = 0; ni < 2; ni++) {
                int cb = wx * 16 + ni * 8;
                bfr[ni][0] = Ksb[(cb + t4) * K_ST + ks + tm4];
                bfr[ni][1] = Ksb[(cb + t4) * K_ST + ks + tm4 + 4];
            }
            #pragma unroll
            for (int mi = 0; mi < 2; mi++)
                #pragma unroll
                for (int ni = 0; ni < 2; ni++)
                    mma_tf32(sacc[mi][ni], afr[mi], bfr[ni]);
        }

        const bool diag = (kt == qt);
        const int k0 = kt * FA_BC;
        #pragma unroll
        for (int mi = 0; mi < 2; mi++) {
            #pragma unroll
            for (int ni = 0; ni < 2; ni++) {
                int rA = wy * 32 + mi * 16 + t4;
                int cA = wx * 16 + ni * 8 + tm4 * 2;
                #pragma unroll
                for (int half = 0; half < 2; half++) {
                    int r = rA + half * 8;
                    float v0 = sacc[mi][ni][half * 2 + 0] * SCALE_;
                    float v1 = sacc[mi][ni][half * 2 + 1] * SCALE_;
                    if (diag) {
                        if (cA > r) v0 = -INFINITY;
                        if (cA + 1 > r) v1 = -INFINITY;
                    }
                    *(float2*)(&Ss[r * S_ST + cA]) = make_float2(v0, v1);
                }
            }
        }
        __syncthreads();

        // Online softmax: 4 threads per row
        {
            const int srow = tid >> 2;
            const int ssub = tid & 3;
            float* Srow = Ss + srow * S_ST + ssub * 16;
            float mo = m_s[srow];
            float mx = mo;
            #pragma unroll
            for (int j = 0; j < 16; j++) mx = fmaxf(mx, Srow[j]);
            mx = fmaxf(mx, __shfl_xor_sync(0xffffffffu, mx, 1));
            mx = fmaxf(mx, __shfl_xor_sync(0xffffffffu, mx, 2));
            float sum = 0.f;
            #pragma unroll
            for (int j = 0; j < 16; j++) {
                float p = __expf(Srow[j] - mx);
                Srow[j] = tf32r(p);
                sum += p;
            }
            sum += __shfl_xor_sync(0xffffffffu, sum, 1);
            sum += __shfl_xor_sync(0xffffffffu, sum, 2);
            if (ssub == 0) {
                float alpha = __expf(mo - mx);
                a_s[srow] = alpha;
                l_s[srow] = l_s[srow] * alpha + sum;
                m_s[srow] = mx;
            }
        }
        __syncthreads();

        // Rescale + PV
        #pragma unroll
        for (int mi = 0; mi < 2; mi++) {
            int rb = wy * 32 + mi * 16 + t4;
            float al0 = a_s[rb];
            float al1 = a_s[rb + 8];
            #pragma unroll
            for (int ni = 0; ni < 4; ni++) {
                o[mi][ni][0] *= al0; o[mi][ni][1] *= al0;
                o[mi][ni][2] *= al1; o[mi][ni][3] *= al1;
            }
        }

        #pragma unroll
        for (int ks = 0; ks < FA_BC; ks += 8) {
            float afr[2][4], bfr[4][2];
            #pragma unroll
            for (int mi = 0; mi < 2; mi++) {
                int rb = wy * 32 + mi * 16;
                afr[mi][0] = Ss[(rb + t4) * S_ST + ks + tm4];
                afr[mi][1] = Ss[(rb + 8 + t4) * S_ST + ks + tm4];
                afr[mi][2] = Ss[(rb + t4) * S_ST + ks + tm4 + 4];
                afr[mi][3] = Ss[(rb + 8 + t4) * S_ST + ks + tm4 + 4];
            }
            #pragma unroll
            for (int ni = 0; ni < 4; ni++) {
                int cb = wx * 32 + ni * 8;
                bfr[ni][0] = Vsb[(ks + tm4) * V_ST + cb + t4];
                bfr[ni][1] = Vsb[(ks + tm4 + 4) * V_ST + cb + t4];
            }
            #pragma unroll
            for (int mi = 0; mi < 2; mi++)
                #pragma unroll
                for (int ni = 0; ni < 4; ni++)
                    mma_tf32(o[mi][ni], afr[mi], bfr[ni]);
        }
    }

    __syncthreads();
    // Epilogue: divide by l, write y (tf32-rounded for gemm_out)
    float* ybase = y + (size_t)b * T_ * C_ + h * D_;
    #pragma unroll
    for (int mi = 0; mi < 2; mi++) {
        int rb = wy * 32 + mi * 16 + t4;
        float inv0 = 1.f / l_s[rb];
        float inv1 = 1.f / l_s[rb + 8];
        #pragma unroll
        for (int ni = 0; ni < 4; ni++) {
            int col = wx * 32 + ni * 8 + tm4 * 2;
            float* d0 = ybase + (size_t)(q0 + rb) * C_ + col;
            float* d1 = ybase + (size_t)(q0 + rb + 8) * C_ + col;
            *(float2*)d0 = make_float2(tf32r(o[mi][ni][0] * inv0), tf32r(o[mi][ni][1] * inv0));
            *(float2*)d1 = make_float2(tf32r(o[mi][ni][2] * inv1), tf32r(o[mi][ni][3] * inv1));
        }
    }
}

// ---------------------------------------------------------------------------
// Launch
// ---------------------------------------------------------------------------
extern "C" void kernel_launch(void* const* d_in, const int* in_sizes, int n_in,
                              void* d_out, int out_size)
{
    const float* x   = (const float*)d_in[0];
    const float* cs  = (const float*)d_in[1];
    const float* sn  = (const float*)d_in[2];
    const float* Wq  = (const float*)d_in[3];
    const float* Wk  = (const float*)d_in[4];
    const float* Wv  = (const float*)d_in[5];
    const float* Wo  = (const float*)d_in[6];
    float* out = (float*)d_out;

    float *qp, *kp, *vp, *yp, *xp, *wqp, *wkp, *wvp, *wop;
    cudaGetSymbolAddress((void**)&qp, g_q);
    cudaGetSymbolAddress((void**)&kp, g_k);
    cudaGetSymbolAddress((void**)&vp, g_v);
    cudaGetSymbolAddress((void**)&yp, g_y);
    cudaGetSymbolAddress((void**)&xp, g_x);
    cudaGetSymbolAddress((void**)&wqp, g_wq);
    cudaGetSymbolAddress((void**)&wkp, g_wk);
    cudaGetSymbolAddress((void**)&wvp, g_wv);
    cudaGetSymbolAddress((void**)&wop, g_wo);

    const int gemm_smem = GEMM_SM_FLOATS * 4;   // 143360 B
    cudaFuncSetAttribute(gemm_qkv, cudaFuncAttributeMaxDynamicSharedMemorySize, gemm_smem);
    cudaFuncSetAttribute(gemm_out, cudaFuncAttributeMaxDynamicSharedMemorySize, gemm_smem);
    const int fa_smem = FA_SMEM_FLOATS * 4;     // 189184 B
    cudaFuncSetAttribute(flash_attn_tf32, cudaFuncAttributeMaxDynamicSharedMemorySize, fa_smem);

    dim3 blk256(256);
    // Pre-round inputs to tf32 (makes hw mma truncation exact)
    {
        int n4;
        n4 = (M_ * C_) / 4;
        tf32_round_kernel<<<(n4 + 255) / 256, blk256>>>((const float4*)x, (float4*)xp, n4);
        n4 = (C_ * C_) / 4;
        tf32_round_kernel<<<(n4 + 255) / 256, blk256>>>((const float4*)Wq, (float4*)wqp, n4);
        n4 = (C_ * KVC_) / 4;
        tf32_round_kernel<<<(n4 + 255) / 256, blk256>>>((const float4*)Wk, (float4*)wkp, n4);
        tf32_round_kernel<<<(n4 + 255) / 256, blk256>>>((const float4*)Wv, (float4*)wvp, n4);
        n4 = (C_ * C_) / 4;
        tf32_round_kernel<<<(n4 + 255) / 256, blk256>>>((const float4*)Wo, (float4*)wop, n4);
    }
    // Fused Q/K/V projections + RoPE + RMSNorm
    gemm_qkv<<<dim3(24, M_ / 128), blk256, gemm_smem>>>(xp, wqp, wkp, wvp, cs, sn, qp, kp, vp);
    // Attention
    flash_attn_tf32<<<dim3(T_ / FA_BR, B_ * H_), blk256, fa_smem>>>(qp, kp, vp, yp);
    // Output projection
    gemm_out<<<dim3(C_ / 128, M_ / 128), blk256, gemm_smem>>>(yp, wop, out);
}